// round 14
// baseline (speedup 1.0000x reference)
#include <cuda_runtime.h>
#include <cuda_bf16.h>
#include <cuda_fp16.h>
#include <cstdint>

#define NN 100000
#define EE 1600000
#define HH 128

#define SCAN_TPB 256
#define SCAN_NPT 4
#define SCAN_NPB (SCAN_TPB * SCAN_NPT)
#define SCAN_NB  ((NN + SCAN_NPB - 1) / SCAN_NPB)

#define TILE_M 256
#define GEMM_TILES ((NN + TILE_M - 1) / TILE_M)   // 391
#define GEMM_THREADS 512

// smem word offsets (32-bit words), XOR-swizzled unpadded layout (R8-verified)
#define WA  (256 * 64)      // 16384 words per A array
#define WB  (128 * 64)      // 8192 words per B array
#define OFF_AH 0
#define OFF_AL (WA)
#define OFF_BH (2 * WA)
#define OFF_BL (2 * WA + WB)
#define GEMM_SMEM ((2 * WA + 2 * WB) * 4)   // 196608 B = 192KB

// ---------------- scratch ----------------
__device__ float  g_res[NN * HH];     // residual (fp32)
__device__ __half g_h[NN * HH];       // GEMM output feeding gather (fp16)
__device__ float  g_y[NN * HH];       // post-agg activation (fp32, feeds GEMM)
__device__ float  g_dinv[NN];
__device__ int    g_deg[NN];
__device__ int    g_rowstart[NN + 1];
__device__ int    g_cursor[NN];
__device__ int    g_csr_src[EE];
__device__ float  g_csr_w[EE];
__device__ int    g_blocksum[SCAN_NB];

// ---------------- helpers ----------------
__device__ __forceinline__ float truncbf(float x) {
    return __uint_as_float(__float_as_uint(x) & 0xFFFF0000u);
}
__device__ __forceinline__ uint32_t packhi(float a, float b) {
    return __byte_perm(__float_as_uint(a), __float_as_uint(b), 0x7632);
}
__device__ __forceinline__ uint32_t packrn(float a, float b) {
    uint32_t d;
    asm("cvt.rn.bf16x2.f32 %0, %1, %2;" : "=r"(d) : "f"(b), "f"(a));
    return d;
}
__device__ __forceinline__ void mma16816(float* c, uint32_t a0, uint32_t a1,
                                         uint32_t a2, uint32_t a3,
                                         uint32_t b0, uint32_t b1) {
    asm volatile(
        "mma.sync.aligned.m16n8k16.row.col.f32.bf16.bf16.f32 "
        "{%0,%1,%2,%3}, {%4,%5,%6,%7}, {%8,%9}, {%0,%1,%2,%3};"
        : "+f"(c[0]), "+f"(c[1]), "+f"(c[2]), "+f"(c[3])
        : "r"(a0), "r"(a1), "r"(a2), "r"(a3), "r"(b0), "r"(b1));
}
// typed 2-element store (fp32 or fp16 output)
__device__ __forceinline__ void st2(float* p, float a, float b) {
    *(float2*)p = make_float2(a, b);
}
__device__ __forceinline__ void st2(__half* p, float a, float b) {
    *(__half2*)p = __floats2half2_rn(a, b);
}

// ---------------- HMMA GEMM (R8-verified): C[M,128] = A[M,128] @ W[128,128] (+bias) ----
// 3-term bf16 split: D = Ah@Bh + Ah@Bl + Al@Bh
// 512 threads = 16 warps; warp tile 32 rows x 64 cols (mg = wid&7, ng = wid>>3).
template <typename OutT>
__global__ void __launch_bounds__(GEMM_THREADS) k_gemm_mma(const float* __restrict__ A,
                                                           const float* __restrict__ W,
                                                           const float* __restrict__ bias,
                                                           OutT* __restrict__ C, int M) {
    extern __shared__ uint32_t smem[];
    uint32_t* sAh = smem + OFF_AH;
    uint32_t* sAl = smem + OFF_AL;
    uint32_t* sBh = smem + OFF_BH;
    uint32_t* sBl = smem + OFF_BL;

    const int tid = threadIdx.x;
    const int wid = tid >> 5;
    const int lane = tid & 31;
    const int row0 = blockIdx.x * TILE_M;

    // ---- stage A: warp w handles rows w*16 .. w*16+15; lane l -> float4 #l ----
    {
#pragma unroll 4
        for (int seg = 0; seg < 16; seg++) {
            int r = wid * 16 + seg;
            int gr = row0 + r;
            float4 v = (gr < M) ? __ldg((const float4*)&A[(size_t)gr * 128] + lane)
                                : make_float4(0.f, 0.f, 0.f, 0.f);
            uint32_t sw = (uint32_t)((r & 7) << 2);
            uint32_t hi0 = packhi(v.x, v.y);
            uint32_t hi1 = packhi(v.z, v.w);
            uint32_t lo0 = packrn(v.x - truncbf(v.x), v.y - truncbf(v.y));
            uint32_t lo1 = packrn(v.z - truncbf(v.z), v.w - truncbf(v.w));
            uint32_t base = (uint32_t)r * 64;
            uint32_t w0 = base + (((uint32_t)(2 * lane)) ^ sw);
            uint32_t w1 = base + (((uint32_t)(2 * lane + 1)) ^ sw);
            sAh[w0] = hi0; sAh[w1] = hi1;
            sAl[w0] = lo0; sAl[w1] = lo1;
        }
    }

    // ---- stage W transposed K-major: word[n][kp] = (W[2kp][n], W[2kp+1][n]) ----
    {
#pragma unroll
        for (int kpi = 0; kpi < 4; kpi++) {
            int kp = wid * 4 + kpi;
            int k = kp * 2;
            const float* r0 = &W[k * 128];
            const float* r1 = &W[(k + 1) * 128];
#pragma unroll
            for (int j = 0; j < 4; j++) {
                int n = lane + 32 * j;
                float w0 = __ldg(&r0[n]);
                float w1 = __ldg(&r1[n]);
                uint32_t hi = packhi(w0, w1);
                uint32_t lo = packrn(w0 - truncbf(w0), w1 - truncbf(w1));
                uint32_t phys = (uint32_t)n * 64 + ((uint32_t)kp ^ (uint32_t)((n & 7) << 2));
                sBh[phys] = hi;
                sBl[phys] = lo;
            }
        }
    }
    __syncthreads();

    // ---- main loop: warp tile 32 x 64 ----
    const int mg = wid & 7;
    const int ng = wid >> 3;
    const int qrow = lane >> 2;
    const int qk = lane & 3;
    const uint32_t sw = (uint32_t)(qrow << 2);

    float acc[2][8][4];
#pragma unroll
    for (int rt = 0; rt < 2; rt++)
#pragma unroll
        for (int nt = 0; nt < 8; nt++)
#pragma unroll
            for (int j = 0; j < 4; j++) acc[rt][nt][j] = 0.f;

#pragma unroll
    for (int ks = 0; ks < 8; ks++) {
        uint32_t kw0 = ((uint32_t)(ks * 8 + qk)) ^ sw;
        uint32_t kw1 = ((uint32_t)(ks * 8 + qk + 4)) ^ sw;
        uint32_t ah[2][4], al[2][4];
#pragma unroll
        for (int rt = 0; rt < 2; rt++) {
            uint32_t b0 = (uint32_t)(mg * 32 + rt * 16 + qrow) * 64;
            uint32_t b8 = b0 + 8 * 64;
            ah[rt][0] = sAh[b0 + kw0];
            ah[rt][1] = sAh[b8 + kw0];
            ah[rt][2] = sAh[b0 + kw1];
            ah[rt][3] = sAh[b8 + kw1];
            al[rt][0] = sAl[b0 + kw0];
            al[rt][1] = sAl[b8 + kw0];
            al[rt][2] = sAl[b0 + kw1];
            al[rt][3] = sAl[b8 + kw1];
        }
#pragma unroll
        for (int nt = 0; nt < 8; nt++) {
            uint32_t nb = (uint32_t)(ng * 64 + nt * 8 + qrow) * 64;
            uint32_t bh0 = sBh[nb + kw0];
            uint32_t bh1 = sBh[nb + kw1];
            uint32_t bl0 = sBl[nb + kw0];
            uint32_t bl1 = sBl[nb + kw1];
#pragma unroll
            for (int rt = 0; rt < 2; rt++) {
                mma16816(acc[rt][nt], ah[rt][0], ah[rt][1], ah[rt][2], ah[rt][3], bh0, bh1);
                mma16816(acc[rt][nt], ah[rt][0], ah[rt][1], ah[rt][2], ah[rt][3], bl0, bl1);
                mma16816(acc[rt][nt], al[rt][0], al[rt][1], al[rt][2], al[rt][3], bh0, bh1);
            }
        }
    }

    // ---- epilogue ----
#pragma unroll
    for (int rt = 0; rt < 2; rt++) {
        int r0 = row0 + mg * 32 + rt * 16 + qrow;
#pragma unroll
        for (int nt = 0; nt < 8; nt++) {
            int col = ng * 64 + nt * 8 + qk * 2;
            float bx = 0.f, by = 0.f;
            if (bias) { bx = __ldg(&bias[col]); by = __ldg(&bias[col + 1]); }
            if (r0 < M)
                st2(&C[(size_t)r0 * 128 + col], acc[rt][nt][0] + bx, acc[rt][nt][1] + by);
            if (r0 + 8 < M)
                st2(&C[(size_t)(r0 + 8) * 128 + col], acc[rt][nt][2] + bx, acc[rt][nt][3] + by);
        }
    }
}

// ---------------- graph structure kernels ----------------
__global__ void k_deg_init() {
    int i = blockIdx.x * blockDim.x + threadIdx.x;
    if (i < NN) g_deg[i] = 1;
}
__global__ void k_count(const int* __restrict__ dst) {
    int e = blockIdx.x * blockDim.x + threadIdx.x;
    if (e < EE) atomicAdd(&g_deg[dst[e]], 1);
}
__global__ void __launch_bounds__(SCAN_TPB) k_scan1() {
    __shared__ int ssum[SCAN_TPB];
    int t = threadIdx.x;
    int base = blockIdx.x * SCAN_NPB + t * SCAN_NPT;
    int s = 0;
#pragma unroll
    for (int c = 0; c < SCAN_NPT; c++) {
        int i = base + c;
        if (i < NN) {
            int d = g_deg[i];
            g_dinv[i] = rsqrtf((float)d);
            s += d - 1;
        }
    }
    ssum[t] = s;
    __syncthreads();
    for (int off = SCAN_TPB / 2; off > 0; off >>= 1) {
        if (t < off) ssum[t] += ssum[t + off];
        __syncthreads();
    }
    if (t == 0) g_blocksum[blockIdx.x] = ssum[0];
}
__global__ void k_scan2() {
    __shared__ int sv[SCAN_NB];
    int t = threadIdx.x;
    if (t < SCAN_NB) sv[t] = g_blocksum[t];
    __syncthreads();
    if (t == 0) {
        int run = 0;
        for (int b = 0; b < SCAN_NB; b++) {
            int v = sv[b];
            g_blocksum[b] = run;
            run += v;
        }
        g_rowstart[NN] = EE;
    }
}
__global__ void __launch_bounds__(SCAN_TPB) k_scan3() {
    __shared__ int ssum[SCAN_TPB];
    int t = threadIdx.x;
    int base = blockIdx.x * SCAN_NPB + t * SCAN_NPT;
    int local[SCAN_NPT];
    int s = 0;
#pragma unroll
    for (int c = 0; c < SCAN_NPT; c++) {
        int i = base + c;
        int d = (i < NN) ? (g_deg[i] - 1) : 0;
        local[c] = d;
        s += d;
    }
    ssum[t] = s;
    __syncthreads();
    for (int off = 1; off < SCAN_TPB; off <<= 1) {
        int v = (t >= off) ? ssum[t - off] : 0;
        __syncthreads();
        ssum[t] += v;
        __syncthreads();
    }
    int run = g_blocksum[blockIdx.x] + ssum[t] - s;
#pragma unroll
    for (int c = 0; c < SCAN_NPT; c++) {
        int i = base + c;
        if (i < NN) {
            g_rowstart[i] = run;
            g_cursor[i]   = run;
            run += local[c];
        }
    }
}
__global__ void k_fill(const int* __restrict__ src, const int* __restrict__ dst) {
    int e = blockIdx.x * blockDim.x + threadIdx.x;
    if (e >= EE) return;
    int s = src[e];
    int d = dst[e];
    int pos = atomicAdd(&g_cursor[d], 1);
    g_csr_src[pos] = s;
    g_csr_w[pos]   = g_dinv[s] * g_dinv[d];
}

// ---------------- aggregation + epilogue: one warp per node, fp16 gather ----------------
// out[i] = relu( sum_j w_j * h[src_j] + dinv^2 * h[i] + bias ) [+ res[i]]
__global__ void __launch_bounds__(256) k_agg(const __half* __restrict__ h,
                                             const float* __restrict__ bias,
                                             const float* __restrict__ res,
                                             float* __restrict__ out) {
    int gw = (blockIdx.x * blockDim.x + threadIdx.x) >> 5;
    int lane = threadIdx.x & 31;
    if (gw >= NN) return;
    int i = gw;

    float di = g_dinv[i];
    float wself = di * di;

    // self row (fp16 -> fp32): lane covers 4 cols via one 8B load
    float4 acc;
    {
        uint2 u = __ldg((const uint2*)(h + (size_t)i * 128) + lane);
        float2 f0 = __half22float2(*(__half2*)&u.x);
        float2 f1 = __half22float2(*(__half2*)&u.y);
        acc.x = f0.x * wself; acc.y = f0.y * wself;
        acc.z = f1.x * wself; acc.w = f1.y * wself;
    }

    int b = g_rowstart[i];
    int e = g_rowstart[i + 1];
    int j = b;
    for (; j + 4 <= e; j += 4) {
        int s0 = g_csr_src[j];
        int s1 = g_csr_src[j + 1];
        int s2 = g_csr_src[j + 2];
        int s3 = g_csr_src[j + 3];
        float w0 = g_csr_w[j];
        float w1 = g_csr_w[j + 1];
        float w2 = g_csr_w[j + 2];
        float w3 = g_csr_w[j + 3];
        uint2 u0 = __ldg((const uint2*)(h + (size_t)s0 * 128) + lane);
        uint2 u1 = __ldg((const uint2*)(h + (size_t)s1 * 128) + lane);
        uint2 u2 = __ldg((const uint2*)(h + (size_t)s2 * 128) + lane);
        uint2 u3 = __ldg((const uint2*)(h + (size_t)s3 * 128) + lane);
        {
            float2 f0 = __half22float2(*(__half2*)&u0.x);
            float2 f1 = __half22float2(*(__half2*)&u0.y);
            acc.x += f0.x * w0; acc.y += f0.y * w0; acc.z += f1.x * w0; acc.w += f1.y * w0;
        }
        {
            float2 f0 = __half22float2(*(__half2*)&u1.x);
            float2 f1 = __half22float2(*(__half2*)&u1.y);
            acc.x += f0.x * w1; acc.y += f0.y * w1; acc.z += f1.x * w1; acc.w += f1.y * w1;
        }
        {
            float2 f0 = __half22float2(*(__half2*)&u2.x);
            float2 f1 = __half22float2(*(__half2*)&u2.y);
            acc.x += f0.x * w2; acc.y += f0.y * w2; acc.z += f1.x * w2; acc.w += f1.y * w2;
        }
        {
            float2 f0 = __half22float2(*(__half2*)&u3.x);
            float2 f1 = __half22float2(*(__half2*)&u3.y);
            acc.x += f0.x * w3; acc.y += f0.y * w3; acc.z += f1.x * w3; acc.w += f1.y * w3;
        }
    }
    for (; j < e; j++) {
        int s   = g_csr_src[j];
        float w = g_csr_w[j];
        uint2 u = __ldg((const uint2*)(h + (size_t)s * 128) + lane);
        float2 f0 = __half22float2(*(__half2*)&u.x);
        float2 f1 = __half22float2(*(__half2*)&u.y);
        acc.x += f0.x * w; acc.y += f0.y * w; acc.z += f1.x * w; acc.w += f1.y * w;
    }

    float4 bb = ((const float4*)bias)[lane];
    float4 o;
    o.x = fmaxf(acc.x + bb.x, 0.f);
    o.y = fmaxf(acc.y + bb.y, 0.f);
    o.z = fmaxf(acc.z + bb.z, 0.f);
    o.w = fmaxf(acc.w + bb.w, 0.f);
    if (res) {
        float4 rv = ((const float4*)&res[(size_t)i * 128])[lane];
        o.x += rv.x; o.y += rv.y; o.z += rv.z; o.w += rv.w;
    }
    ((float4*)&out[(size_t)i * 128])[lane] = o;
}

// ---------------- host launcher ----------------
extern "C" void kernel_launch(void* const* d_in, const int* in_sizes, int n_in,
                              void* d_out, int out_size) {
    const float* x  = (const float*)d_in[0];
    const int*   ei = (const int*)d_in[1];
    const float* W0 = (const float*)d_in[2];
    const float* b0 = (const float*)d_in[3];
    const float* W1 = (const float*)d_in[4];
    const float* b1 = (const float*)d_in[5];
    const float* W2 = (const float*)d_in[6];
    const float* b2 = (const float*)d_in[7];
    const float* Wr = (const float*)d_in[8];
    const float* br = (const float*)d_in[9];
    float* out = (float*)d_out;

    const int* src = ei;
    const int* dst = ei + EE;

    float *res_p, *y_p;
    __half* h_p;
    cudaGetSymbolAddress((void**)&res_p, g_res);
    cudaGetSymbolAddress((void**)&h_p, g_h);
    cudaGetSymbolAddress((void**)&y_p, g_y);

    cudaFuncSetAttribute(k_gemm_mma<float>, cudaFuncAttributeMaxDynamicSharedMemorySize, GEMM_SMEM);
    cudaFuncSetAttribute(k_gemm_mma<__half>, cudaFuncAttributeMaxDynamicSharedMemorySize, GEMM_SMEM);

    const int AB = (NN + 7) / 8;
    const int EB = (EE + 255) / 256;
    const int NB = (NN + 255) / 256;

    k_deg_init<<<NB, 256>>>();
    k_count<<<EB, 256>>>(dst);
    k_scan1<<<SCAN_NB, SCAN_TPB>>>();

    // layer-0 GEMM placed 4th so the profiler (which captures launch #4) sees it
    k_gemm_mma<__half><<<GEMM_TILES, GEMM_THREADS, GEMM_SMEM>>>(x, W0, nullptr, h_p, NN);

    k_scan2<<<1, 128>>>();
    k_scan3<<<SCAN_NB, SCAN_TPB>>>();
    k_fill<<<EB, 256>>>(src, dst);

    // residual = x @ Wr + br (fp32 output)
    k_gemm_mma<float><<<GEMM_TILES, GEMM_THREADS, GEMM_SMEM>>>(x, Wr, br, res_p, NN);

    // layer 0 aggregation
    k_agg<<<AB, 256>>>(h_p, b0, res_p, y_p);

    // layer 1
    k_gemm_mma<__half><<<GEMM_TILES, GEMM_THREADS, GEMM_SMEM>>>(y_p, W1, nullptr, h_p, NN);
    k_agg<<<AB, 256>>>(h_p, b1, nullptr, y_p);

    // layer 2
    k_gemm_mma<__half><<<GEMM_TILES, GEMM_THREADS, GEMM_SMEM>>>(y_p, W2, nullptr, h_p, NN);
    k_agg<<<AB, 256>>>(h_p, b2, nullptr, out);
}

// round 15
// speedup vs baseline: 1.3077x; 1.3077x over previous
#include <cuda_runtime.h>
#include <cuda_bf16.h>
#include <cstdint>

#define NN 100000
#define EE 1600000
#define HH 128

#define SCAN_TPB 256
#define SCAN_NPT 4
#define SCAN_NPB (SCAN_TPB * SCAN_NPT)
#define SCAN_NB  ((NN + SCAN_NPB - 1) / SCAN_NPB)

#define TILE_M 256
#define GEMM_TILES ((NN + TILE_M - 1) / TILE_M)   // 391
#define GEMM_THREADS 512

// smem word offsets (32-bit words), XOR-swizzled unpadded layout (R8-verified)
#define WA  (256 * 64)      // 16384 words per A array
#define WB  (128 * 64)      // 8192 words per B array
#define OFF_AH 0
#define OFF_AL (WA)
#define OFF_BH (2 * WA)
#define OFF_BL (2 * WA + WB)
#define GEMM_SMEM ((2 * WA + 2 * WB) * 4)   // 196608 B = 192KB

// ---------------- scratch ----------------
__device__ float g_res[NN * HH];
__device__ float g_h[NN * HH];
__device__ float g_y[NN * HH];
__device__ float g_dinv[NN];
__device__ int   g_deg[NN];
__device__ int   g_rowstart[NN + 1];
__device__ int   g_cursor[NN];
__device__ int   g_csr_src[EE];
__device__ float g_csr_w[EE];
__device__ int   g_blocksum[SCAN_NB];

// ---------------- helpers ----------------
__device__ __forceinline__ float truncbf(float x) {
    return __uint_as_float(__float_as_uint(x) & 0xFFFF0000u);
}
__device__ __forceinline__ uint32_t packhi(float a, float b) {
    return __byte_perm(__float_as_uint(a), __float_as_uint(b), 0x7632);
}
__device__ __forceinline__ uint32_t packrn(float a, float b) {
    uint32_t d;
    asm("cvt.rn.bf16x2.f32 %0, %1, %2;" : "=r"(d) : "f"(b), "f"(a));
    return d;
}
__device__ __forceinline__ void mma16816(float* c, uint32_t a0, uint32_t a1,
                                         uint32_t a2, uint32_t a3,
                                         uint32_t b0, uint32_t b1) {
    asm volatile(
        "mma.sync.aligned.m16n8k16.row.col.f32.bf16.bf16.f32 "
        "{%0,%1,%2,%3}, {%4,%5,%6,%7}, {%8,%9}, {%0,%1,%2,%3};"
        : "+f"(c[0]), "+f"(c[1]), "+f"(c[2]), "+f"(c[3])
        : "r"(a0), "r"(a1), "r"(a2), "r"(a3), "r"(b0), "r"(b1));
}

// ---------------- HMMA GEMM (R8-verified): C[M,128] = A[M,128] @ W[128,128] (+bias) ----
// 3-term bf16 split: D = Ah@Bh + Ah@Bl + Al@Bh
// 512 threads = 16 warps; warp tile 32 rows x 64 cols (mg = wid&7, ng = wid>>3).
__global__ void __launch_bounds__(GEMM_THREADS) k_gemm_mma(const float* __restrict__ A,
                                                           const float* __restrict__ W,
                                                           const float* __restrict__ bias,
                                                           float* __restrict__ C, int M) {
    extern __shared__ uint32_t smem[];
    uint32_t* sAh = smem + OFF_AH;
    uint32_t* sAl = smem + OFF_AL;
    uint32_t* sBh = smem + OFF_BH;
    uint32_t* sBl = smem + OFF_BL;

    const int tid = threadIdx.x;
    const int wid = tid >> 5;
    const int lane = tid & 31;
    const int row0 = blockIdx.x * TILE_M;

    // ---- stage A: warp w handles rows w*16 .. w*16+15; lane l -> float4 #l ----
    {
#pragma unroll 4
        for (int seg = 0; seg < 16; seg++) {
            int r = wid * 16 + seg;
            int gr = row0 + r;
            float4 v = (gr < M) ? __ldg((const float4*)&A[(size_t)gr * 128] + lane)
                                : make_float4(0.f, 0.f, 0.f, 0.f);
            uint32_t sw = (uint32_t)((r & 7) << 2);
            uint32_t hi0 = packhi(v.x, v.y);
            uint32_t hi1 = packhi(v.z, v.w);
            uint32_t lo0 = packrn(v.x - truncbf(v.x), v.y - truncbf(v.y));
            uint32_t lo1 = packrn(v.z - truncbf(v.z), v.w - truncbf(v.w));
            uint32_t base = (uint32_t)r * 64;
            uint32_t w0 = base + (((uint32_t)(2 * lane)) ^ sw);
            uint32_t w1 = base + (((uint32_t)(2 * lane + 1)) ^ sw);
            sAh[w0] = hi0; sAh[w1] = hi1;
            sAl[w0] = lo0; sAl[w1] = lo1;
        }
    }

    // ---- stage W transposed K-major: word[n][kp] = (W[2kp][n], W[2kp+1][n]) ----
    {
#pragma unroll
        for (int kpi = 0; kpi < 4; kpi++) {
            int kp = wid * 4 + kpi;
            int k = kp * 2;
            const float* r0 = &W[k * 128];
            const float* r1 = &W[(k + 1) * 128];
#pragma unroll
            for (int j = 0; j < 4; j++) {
                int n = lane + 32 * j;
                float w0 = __ldg(&r0[n]);
                float w1 = __ldg(&r1[n]);
                uint32_t hi = packhi(w0, w1);
                uint32_t lo = packrn(w0 - truncbf(w0), w1 - truncbf(w1));
                uint32_t phys = (uint32_t)n * 64 + ((uint32_t)kp ^ (uint32_t)((n & 7) << 2));
                sBh[phys] = hi;
                sBl[phys] = lo;
            }
        }
    }
    __syncthreads();

    // ---- main loop: warp tile 32 x 64 ----
    const int mg = wid & 7;
    const int ng = wid >> 3;
    const int qrow = lane >> 2;
    const int qk = lane & 3;
    const uint32_t sw = (uint32_t)(qrow << 2);

    float acc[2][8][4];
#pragma unroll
    for (int rt = 0; rt < 2; rt++)
#pragma unroll
        for (int nt = 0; nt < 8; nt++)
#pragma unroll
            for (int j = 0; j < 4; j++) acc[rt][nt][j] = 0.f;

#pragma unroll
    for (int ks = 0; ks < 8; ks++) {
        uint32_t kw0 = ((uint32_t)(ks * 8 + qk)) ^ sw;
        uint32_t kw1 = ((uint32_t)(ks * 8 + qk + 4)) ^ sw;
        uint32_t ah[2][4], al[2][4];
#pragma unroll
        for (int rt = 0; rt < 2; rt++) {
            uint32_t b0 = (uint32_t)(mg * 32 + rt * 16 + qrow) * 64;
            uint32_t b8 = b0 + 8 * 64;
            ah[rt][0] = sAh[b0 + kw0];
            ah[rt][1] = sAh[b8 + kw0];
            ah[rt][2] = sAh[b0 + kw1];
            ah[rt][3] = sAh[b8 + kw1];
            al[rt][0] = sAl[b0 + kw0];
            al[rt][1] = sAl[b8 + kw0];
            al[rt][2] = sAl[b0 + kw1];
            al[rt][3] = sAl[b8 + kw1];
        }
#pragma unroll
        for (int nt = 0; nt < 8; nt++) {
            uint32_t nb = (uint32_t)(ng * 64 + nt * 8 + qrow) * 64;
            uint32_t bh0 = sBh[nb + kw0];
            uint32_t bh1 = sBh[nb + kw1];
            uint32_t bl0 = sBl[nb + kw0];
            uint32_t bl1 = sBl[nb + kw1];
#pragma unroll
            for (int rt = 0; rt < 2; rt++) {
                mma16816(acc[rt][nt], ah[rt][0], ah[rt][1], ah[rt][2], ah[rt][3], bh0, bh1);
                mma16816(acc[rt][nt], ah[rt][0], ah[rt][1], ah[rt][2], ah[rt][3], bl0, bl1);
                mma16816(acc[rt][nt], al[rt][0], al[rt][1], al[rt][2], al[rt][3], bh0, bh1);
            }
        }
    }

    // ---- epilogue ----
#pragma unroll
    for (int rt = 0; rt < 2; rt++) {
        int r0 = row0 + mg * 32 + rt * 16 + qrow;
#pragma unroll
        for (int nt = 0; nt < 8; nt++) {
            int col = ng * 64 + nt * 8 + qk * 2;
            float bx = 0.f, by = 0.f;
            if (bias) { bx = __ldg(&bias[col]); by = __ldg(&bias[col + 1]); }
            if (r0 < M) {
                float2 o = make_float2(acc[rt][nt][0] + bx, acc[rt][nt][1] + by);
                *(float2*)&C[(size_t)r0 * 128 + col] = o;
            }
            if (r0 + 8 < M) {
                float2 o = make_float2(acc[rt][nt][2] + bx, acc[rt][nt][3] + by);
                *(float2*)&C[(size_t)(r0 + 8) * 128 + col] = o;
            }
        }
    }
}

// ---------------- graph structure kernels ----------------
__global__ void k_deg_init() {
    int i = blockIdx.x * blockDim.x + threadIdx.x;
    if (i < NN) g_deg[i] = 1;
}
__global__ void k_count(const int* __restrict__ dst) {
    int e = blockIdx.x * blockDim.x + threadIdx.x;
    if (e < EE) atomicAdd(&g_deg[dst[e]], 1);
}
__global__ void __launch_bounds__(SCAN_TPB) k_scan1() {
    __shared__ int ssum[SCAN_TPB];
    int t = threadIdx.x;
    int base = blockIdx.x * SCAN_NPB + t * SCAN_NPT;
    int s = 0;
#pragma unroll
    for (int c = 0; c < SCAN_NPT; c++) {
        int i = base + c;
        if (i < NN) {
            int d = g_deg[i];
            g_dinv[i] = rsqrtf((float)d);
            s += d - 1;
        }
    }
    ssum[t] = s;
    __syncthreads();
    for (int off = SCAN_TPB / 2; off > 0; off >>= 1) {
        if (t < off) ssum[t] += ssum[t + off];
        __syncthreads();
    }
    if (t == 0) g_blocksum[blockIdx.x] = ssum[0];
}
__global__ void k_scan2() {
    __shared__ int sv[SCAN_NB];
    int t = threadIdx.x;
    if (t < SCAN_NB) sv[t] = g_blocksum[t];
    __syncthreads();
    if (t == 0) {
        int run = 0;
        for (int b = 0; b < SCAN_NB; b++) {
            int v = sv[b];
            g_blocksum[b] = run;
            run += v;
        }
        g_rowstart[NN] = EE;
    }
}
__global__ void __launch_bounds__(SCAN_TPB) k_scan3() {
    __shared__ int ssum[SCAN_TPB];
    int t = threadIdx.x;
    int base = blockIdx.x * SCAN_NPB + t * SCAN_NPT;
    int local[SCAN_NPT];
    int s = 0;
#pragma unroll
    for (int c = 0; c < SCAN_NPT; c++) {
        int i = base + c;
        int d = (i < NN) ? (g_deg[i] - 1) : 0;
        local[c] = d;
        s += d;
    }
    ssum[t] = s;
    __syncthreads();
    for (int off = 1; off < SCAN_TPB; off <<= 1) {
        int v = (t >= off) ? ssum[t - off] : 0;
        __syncthreads();
        ssum[t] += v;
        __syncthreads();
    }
    int run = g_blocksum[blockIdx.x] + ssum[t] - s;
#pragma unroll
    for (int c = 0; c < SCAN_NPT; c++) {
        int i = base + c;
        if (i < NN) {
            g_rowstart[i] = run;
            g_cursor[i]   = run;
            run += local[c];
        }
    }
}
__global__ void k_fill(const int* __restrict__ src, const int* __restrict__ dst) {
    int e = blockIdx.x * blockDim.x + threadIdx.x;
    if (e >= EE) return;
    int s = src[e];
    int d = dst[e];
    int pos = atomicAdd(&g_cursor[d], 1);
    g_csr_src[pos] = s;
    g_csr_w[pos]   = g_dinv[s] * g_dinv[d];
}

// ---------------- aggregation + epilogue: one warp per node, unroll 8 ----------------
__global__ void __launch_bounds__(256) k_agg(const float* __restrict__ h,
                                             const float* __restrict__ bias,
                                             const float* __restrict__ res,
                                             float* __restrict__ out) {
    int gw = (blockIdx.x * blockDim.x + threadIdx.x) >> 5;
    int lane = threadIdx.x & 31;
    if (gw >= NN) return;
    int i = gw;

    float di = g_dinv[i];
    float wself = di * di;
    const float4* hrow = (const float4*)&h[(size_t)i * 128];
    float4 acc = hrow[lane];
    acc.x *= wself; acc.y *= wself; acc.z *= wself; acc.w *= wself;

    int b = g_rowstart[i];
    int e = g_rowstart[i + 1];
    int j = b;
    // unroll x8: batch indices+weights, then 8 independent gathers in flight
    for (; j + 8 <= e; j += 8) {
        int sidx[8];
        float wv[8];
#pragma unroll
        for (int u = 0; u < 8; u++) {
            sidx[u] = g_csr_src[j + u];
            wv[u] = g_csr_w[j + u];
        }
        float4 v[8];
#pragma unroll
        for (int u = 0; u < 8; u++)
            v[u] = ((const float4*)&h[(size_t)sidx[u] * 128])[lane];
#pragma unroll
        for (int u = 0; u < 8; u++) {
            acc.x += v[u].x * wv[u];
            acc.y += v[u].y * wv[u];
            acc.z += v[u].z * wv[u];
            acc.w += v[u].w * wv[u];
        }
    }
    for (; j + 4 <= e; j += 4) {
        int s0 = g_csr_src[j];
        int s1 = g_csr_src[j + 1];
        int s2 = g_csr_src[j + 2];
        int s3 = g_csr_src[j + 3];
        float w0 = g_csr_w[j];
        float w1 = g_csr_w[j + 1];
        float w2 = g_csr_w[j + 2];
        float w3 = g_csr_w[j + 3];
        float4 v0 = ((const float4*)&h[(size_t)s0 * 128])[lane];
        float4 v1 = ((const float4*)&h[(size_t)s1 * 128])[lane];
        float4 v2 = ((const float4*)&h[(size_t)s2 * 128])[lane];
        float4 v3 = ((const float4*)&h[(size_t)s3 * 128])[lane];
        acc.x += v0.x * w0; acc.y += v0.y * w0; acc.z += v0.z * w0; acc.w += v0.w * w0;
        acc.x += v1.x * w1; acc.y += v1.y * w1; acc.z += v1.z * w1; acc.w += v1.w * w1;
        acc.x += v2.x * w2; acc.y += v2.y * w2; acc.z += v2.z * w2; acc.w += v2.w * w2;
        acc.x += v3.x * w3; acc.y += v3.y * w3; acc.z += v3.z * w3; acc.w += v3.w * w3;
    }
    for (; j < e; j++) {
        int s   = g_csr_src[j];
        float w = g_csr_w[j];
        float4 v = ((const float4*)&h[(size_t)s * 128])[lane];
        acc.x += v.x * w;
        acc.y += v.y * w;
        acc.z += v.z * w;
        acc.w += v.w * w;
    }

    float4 bb = ((const float4*)bias)[lane];
    float4 o;
    o.x = fmaxf(acc.x + bb.x, 0.f);
    o.y = fmaxf(acc.y + bb.y, 0.f);
    o.z = fmaxf(acc.z + bb.z, 0.f);
    o.w = fmaxf(acc.w + bb.w, 0.f);
    if (res) {
        float4 rv = ((const float4*)&res[(size_t)i * 128])[lane];
        o.x += rv.x; o.y += rv.y; o.z += rv.z; o.w += rv.w;
    }
    ((float4*)&out[(size_t)i * 128])[lane] = o;
}

// ---------------- host launcher ----------------
extern "C" void kernel_launch(void* const* d_in, const int* in_sizes, int n_in,
                              void* d_out, int out_size) {
    const float* x  = (const float*)d_in[0];
    const int*   ei = (const int*)d_in[1];
    const float* W0 = (const float*)d_in[2];
    const float* b0 = (const float*)d_in[3];
    const float* W1 = (const float*)d_in[4];
    const float* b1 = (const float*)d_in[5];
    const float* W2 = (const float*)d_in[6];
    const float* b2 = (const float*)d_in[7];
    const float* Wr = (const float*)d_in[8];
    const float* br = (const float*)d_in[9];
    float* out = (float*)d_out;

    const int* src = ei;
    const int* dst = ei + EE;

    float *res_p, *h_p, *y_p;
    cudaGetSymbolAddress((void**)&res_p, g_res);
    cudaGetSymbolAddress((void**)&h_p, g_h);
    cudaGetSymbolAddress((void**)&y_p, g_y);

    cudaFuncSetAttribute(k_gemm_mma, cudaFuncAttributeMaxDynamicSharedMemorySize, GEMM_SMEM);

    const int AB = (NN + 7) / 8;
    const int EB = (EE + 255) / 256;
    const int NB = (NN + 255) / 256;

    k_deg_init<<<NB, 256>>>();
    k_count<<<EB, 256>>>(dst);
    k_scan1<<<SCAN_NB, SCAN_TPB>>>();

    // residual GEMM placed 4th so the profiler (which captures launch #4) sees it
    k_gemm_mma<<<GEMM_TILES, GEMM_THREADS, GEMM_SMEM>>>(x, Wr, br, res_p, NN);

    k_scan2<<<1, 128>>>();
    k_scan3<<<SCAN_NB, SCAN_TPB>>>();
    k_fill<<<EB, 256>>>(src, dst);

    // layer 0
    k_gemm_mma<<<GEMM_TILES, GEMM_THREADS, GEMM_SMEM>>>(x, W0, nullptr, h_p, NN);
    k_agg<<<AB, 256>>>(h_p, b0, res_p, y_p);

    // layer 1
    k_gemm_mma<<<GEMM_TILES, GEMM_THREADS, GEMM_SMEM>>>(y_p, W1, nullptr, h_p, NN);
    k_agg<<<AB, 256>>>(h_p, b1, nullptr, y_p);

    // layer 2
    k_gemm_mma<<<GEMM_TILES, GEMM_THREADS, GEMM_SMEM>>>(y_p, W2, nullptr, h_p, NN);
    k_agg<<<AB, 256>>>(h_p, b2, nullptr, out);
}

// round 16
// speedup vs baseline: 1.4554x; 1.1130x over previous
#include <cuda_runtime.h>
#include <cuda_bf16.h>
#include <cuda_fp16.h>
#include <cstdint>

#define NN 100000
#define EE 1600000
#define HH 128

#define SCAN_TPB 256
#define SCAN_NPT 4
#define SCAN_NPB (SCAN_TPB * SCAN_NPT)
#define SCAN_NB  ((NN + SCAN_NPB - 1) / SCAN_NPB)

#define TILE_M 256
#define GEMM_TILES ((NN + TILE_M - 1) / TILE_M)   // 391
#define GEMM_THREADS 512

// smem word offsets (32-bit words), XOR-swizzled unpadded layout (R8-verified)
#define WA  (256 * 64)      // 16384 words per A array
#define WB  (128 * 64)      // 8192 words per B array
#define OFF_AH 0
#define OFF_AL (WA)
#define OFF_BH (2 * WA)
#define OFF_BL (2 * WA + WB)
#define GEMM_SMEM ((2 * WA + 2 * WB) * 4)   // 196608 B = 192KB

// ---------------- scratch ----------------
__device__ float  g_res[NN * HH];     // residual (fp32)
__device__ __half g_h[NN * HH];       // GEMM output feeding gather (fp16)
__device__ float  g_y[NN * HH];       // post-agg activation (fp32, feeds GEMM)
__device__ float  g_dinv[NN];
__device__ int    g_deg[NN];
__device__ int    g_rowstart[NN + 1];
__device__ int    g_cursor[NN];
__device__ int    g_csr_src[EE];
__device__ float  g_csr_w[EE];
__device__ int    g_blocksum[SCAN_NB];

// ---------------- helpers ----------------
__device__ __forceinline__ float truncbf(float x) {
    return __uint_as_float(__float_as_uint(x) & 0xFFFF0000u);
}
__device__ __forceinline__ uint32_t packhi(float a, float b) {
    return __byte_perm(__float_as_uint(a), __float_as_uint(b), 0x7632);
}
__device__ __forceinline__ uint32_t packrn(float a, float b) {
    uint32_t d;
    asm("cvt.rn.bf16x2.f32 %0, %1, %2;" : "=r"(d) : "f"(b), "f"(a));
    return d;
}
__device__ __forceinline__ void mma16816(float* c, uint32_t a0, uint32_t a1,
                                         uint32_t a2, uint32_t a3,
                                         uint32_t b0, uint32_t b1) {
    asm volatile(
        "mma.sync.aligned.m16n8k16.row.col.f32.bf16.bf16.f32 "
        "{%0,%1,%2,%3}, {%4,%5,%6,%7}, {%8,%9}, {%0,%1,%2,%3};"
        : "+f"(c[0]), "+f"(c[1]), "+f"(c[2]), "+f"(c[3])
        : "r"(a0), "r"(a1), "r"(a2), "r"(a3), "r"(b0), "r"(b1));
}
// typed 2-element store (fp32 or fp16 output)
__device__ __forceinline__ void st2(float* p, float a, float b) {
    *(float2*)p = make_float2(a, b);
}
__device__ __forceinline__ void st2(__half* p, float a, float b) {
    *(__half2*)p = __floats2half2_rn(a, b);
}

// ---------------- HMMA GEMM (R8-verified): C[M,128] = A[M,128] @ W[128,128] (+bias) ----
// 3-term bf16 split: D = Ah@Bh + Ah@Bl + Al@Bh
// 512 threads = 16 warps; warp tile 32 rows x 64 cols (mg = wid&7, ng = wid>>3).
template <typename OutT>
__global__ void __launch_bounds__(GEMM_THREADS) k_gemm_mma(const float* __restrict__ A,
                                                           const float* __restrict__ W,
                                                           const float* __restrict__ bias,
                                                           OutT* __restrict__ C, int M) {
    extern __shared__ uint32_t smem[];
    uint32_t* sAh = smem + OFF_AH;
    uint32_t* sAl = smem + OFF_AL;
    uint32_t* sBh = smem + OFF_BH;
    uint32_t* sBl = smem + OFF_BL;

    const int tid = threadIdx.x;
    const int wid = tid >> 5;
    const int lane = tid & 31;
    const int row0 = blockIdx.x * TILE_M;

    // ---- stage A: warp w handles rows w*16 .. w*16+15; lane l -> float4 #l ----
    {
#pragma unroll 4
        for (int seg = 0; seg < 16; seg++) {
            int r = wid * 16 + seg;
            int gr = row0 + r;
            float4 v = (gr < M) ? __ldg((const float4*)&A[(size_t)gr * 128] + lane)
                                : make_float4(0.f, 0.f, 0.f, 0.f);
            uint32_t sw = (uint32_t)((r & 7) << 2);
            uint32_t hi0 = packhi(v.x, v.y);
            uint32_t hi1 = packhi(v.z, v.w);
            uint32_t lo0 = packrn(v.x - truncbf(v.x), v.y - truncbf(v.y));
            uint32_t lo1 = packrn(v.z - truncbf(v.z), v.w - truncbf(v.w));
            uint32_t base = (uint32_t)r * 64;
            uint32_t w0 = base + (((uint32_t)(2 * lane)) ^ sw);
            uint32_t w1 = base + (((uint32_t)(2 * lane + 1)) ^ sw);
            sAh[w0] = hi0; sAh[w1] = hi1;
            sAl[w0] = lo0; sAl[w1] = lo1;
        }
    }

    // ---- stage W transposed K-major: word[n][kp] = (W[2kp][n], W[2kp+1][n]) ----
    {
#pragma unroll
        for (int kpi = 0; kpi < 4; kpi++) {
            int kp = wid * 4 + kpi;
            int k = kp * 2;
            const float* r0 = &W[k * 128];
            const float* r1 = &W[(k + 1) * 128];
#pragma unroll
            for (int j = 0; j < 4; j++) {
                int n = lane + 32 * j;
                float w0 = __ldg(&r0[n]);
                float w1 = __ldg(&r1[n]);
                uint32_t hi = packhi(w0, w1);
                uint32_t lo = packrn(w0 - truncbf(w0), w1 - truncbf(w1));
                uint32_t phys = (uint32_t)n * 64 + ((uint32_t)kp ^ (uint32_t)((n & 7) << 2));
                sBh[phys] = hi;
                sBl[phys] = lo;
            }
        }
    }
    __syncthreads();

    // ---- main loop: warp tile 32 x 64 ----
    const int mg = wid & 7;
    const int ng = wid >> 3;
    const int qrow = lane >> 2;
    const int qk = lane & 3;
    const uint32_t sw = (uint32_t)(qrow << 2);

    float acc[2][8][4];
#pragma unroll
    for (int rt = 0; rt < 2; rt++)
#pragma unroll
        for (int nt = 0; nt < 8; nt++)
#pragma unroll
            for (int j = 0; j < 4; j++) acc[rt][nt][j] = 0.f;

#pragma unroll
    for (int ks = 0; ks < 8; ks++) {
        uint32_t kw0 = ((uint32_t)(ks * 8 + qk)) ^ sw;
        uint32_t kw1 = ((uint32_t)(ks * 8 + qk + 4)) ^ sw;
        uint32_t ah[2][4], al[2][4];
#pragma unroll
        for (int rt = 0; rt < 2; rt++) {
            uint32_t b0 = (uint32_t)(mg * 32 + rt * 16 + qrow) * 64;
            uint32_t b8 = b0 + 8 * 64;
            ah[rt][0] = sAh[b0 + kw0];
            ah[rt][1] = sAh[b8 + kw0];
            ah[rt][2] = sAh[b0 + kw1];
            ah[rt][3] = sAh[b8 + kw1];
            al[rt][0] = sAl[b0 + kw0];
            al[rt][1] = sAl[b8 + kw0];
            al[rt][2] = sAl[b0 + kw1];
            al[rt][3] = sAl[b8 + kw1];
        }
#pragma unroll
        for (int nt = 0; nt < 8; nt++) {
            uint32_t nb = (uint32_t)(ng * 64 + nt * 8 + qrow) * 64;
            uint32_t bh0 = sBh[nb + kw0];
            uint32_t bh1 = sBh[nb + kw1];
            uint32_t bl0 = sBl[nb + kw0];
            uint32_t bl1 = sBl[nb + kw1];
#pragma unroll
            for (int rt = 0; rt < 2; rt++) {
                mma16816(acc[rt][nt], ah[rt][0], ah[rt][1], ah[rt][2], ah[rt][3], bh0, bh1);
                mma16816(acc[rt][nt], ah[rt][0], ah[rt][1], ah[rt][2], ah[rt][3], bl0, bl1);
                mma16816(acc[rt][nt], al[rt][0], al[rt][1], al[rt][2], al[rt][3], bh0, bh1);
            }
        }
    }

    // ---- epilogue ----
#pragma unroll
    for (int rt = 0; rt < 2; rt++) {
        int r0 = row0 + mg * 32 + rt * 16 + qrow;
#pragma unroll
        for (int nt = 0; nt < 8; nt++) {
            int col = ng * 64 + nt * 8 + qk * 2;
            float bx = 0.f, by = 0.f;
            if (bias) { bx = __ldg(&bias[col]); by = __ldg(&bias[col + 1]); }
            if (r0 < M)
                st2(&C[(size_t)r0 * 128 + col], acc[rt][nt][0] + bx, acc[rt][nt][1] + by);
            if (r0 + 8 < M)
                st2(&C[(size_t)(r0 + 8) * 128 + col], acc[rt][nt][2] + bx, acc[rt][nt][3] + by);
        }
    }
}

// ---------------- graph structure kernels ----------------
__global__ void k_deg_init() {
    int i = blockIdx.x * blockDim.x + threadIdx.x;
    if (i < NN) g_deg[i] = 1;
}
__global__ void k_count(const int* __restrict__ dst) {
    int e = blockIdx.x * blockDim.x + threadIdx.x;
    if (e < EE) atomicAdd(&g_deg[dst[e]], 1);
}
__global__ void __launch_bounds__(SCAN_TPB) k_scan1() {
    __shared__ int ssum[SCAN_TPB];
    int t = threadIdx.x;
    int base = blockIdx.x * SCAN_NPB + t * SCAN_NPT;
    int s = 0;
#pragma unroll
    for (int c = 0; c < SCAN_NPT; c++) {
        int i = base + c;
        if (i < NN) {
            int d = g_deg[i];
            g_dinv[i] = rsqrtf((float)d);
            s += d - 1;
        }
    }
    ssum[t] = s;
    __syncthreads();
    for (int off = SCAN_TPB / 2; off > 0; off >>= 1) {
        if (t < off) ssum[t] += ssum[t + off];
        __syncthreads();
    }
    if (t == 0) g_blocksum[blockIdx.x] = ssum[0];
}
__global__ void k_scan2() {
    __shared__ int sv[SCAN_NB];
    int t = threadIdx.x;
    if (t < SCAN_NB) sv[t] = g_blocksum[t];
    __syncthreads();
    if (t == 0) {
        int run = 0;
        for (int b = 0; b < SCAN_NB; b++) {
            int v = sv[b];
            g_blocksum[b] = run;
            run += v;
        }
        g_rowstart[NN] = EE;
    }
}
__global__ void __launch_bounds__(SCAN_TPB) k_scan3() {
    __shared__ int ssum[SCAN_TPB];
    int t = threadIdx.x;
    int base = blockIdx.x * SCAN_NPB + t * SCAN_NPT;
    int local[SCAN_NPT];
    int s = 0;
#pragma unroll
    for (int c = 0; c < SCAN_NPT; c++) {
        int i = base + c;
        int d = (i < NN) ? (g_deg[i] - 1) : 0;
        local[c] = d;
        s += d;
    }
    ssum[t] = s;
    __syncthreads();
    for (int off = 1; off < SCAN_TPB; off <<= 1) {
        int v = (t >= off) ? ssum[t - off] : 0;
        __syncthreads();
        ssum[t] += v;
        __syncthreads();
    }
    int run = g_blocksum[blockIdx.x] + ssum[t] - s;
#pragma unroll
    for (int c = 0; c < SCAN_NPT; c++) {
        int i = base + c;
        if (i < NN) {
            g_rowstart[i] = run;
            g_cursor[i]   = run;
            run += local[c];
        }
    }
}
__global__ void k_fill(const int* __restrict__ src, const int* __restrict__ dst) {
    int e = blockIdx.x * blockDim.x + threadIdx.x;
    if (e >= EE) return;
    int s = src[e];
    int d = dst[e];
    int pos = atomicAdd(&g_cursor[d], 1);
    g_csr_src[pos] = s;
    g_csr_w[pos]   = g_dinv[s] * g_dinv[d];
}

// ---------------- aggregation: one warp per node, fp16 gather, unroll 8 ----------------
__global__ void __launch_bounds__(256) k_agg(const __half* __restrict__ h,
                                             const float* __restrict__ bias,
                                             const float* __restrict__ res,
                                             float* __restrict__ out) {
    int gw = (blockIdx.x * blockDim.x + threadIdx.x) >> 5;
    int lane = threadIdx.x & 31;
    if (gw >= NN) return;
    int i = gw;

    float di = g_dinv[i];
    float wself = di * di;

    float4 acc;
    {
        uint2 u = __ldg((const uint2*)(h + (size_t)i * 128) + lane);
        float2 f0 = __half22float2(*(__half2*)&u.x);
        float2 f1 = __half22float2(*(__half2*)&u.y);
        acc.x = f0.x * wself; acc.y = f0.y * wself;
        acc.z = f1.x * wself; acc.w = f1.y * wself;
    }

    int b = g_rowstart[i];
    int e = g_rowstart[i + 1];
    int j = b;
    // unroll x8: batch indices+weights, then 8 independent gathers in flight
    for (; j + 8 <= e; j += 8) {
        int sidx[8];
        float wv[8];
#pragma unroll
        for (int u = 0; u < 8; u++) {
            sidx[u] = g_csr_src[j + u];
            wv[u] = g_csr_w[j + u];
        }
        uint2 v[8];
#pragma unroll
        for (int u = 0; u < 8; u++)
            v[u] = __ldg((const uint2*)(h + (size_t)sidx[u] * 128) + lane);
#pragma unroll
        for (int u = 0; u < 8; u++) {
            float2 f0 = __half22float2(*(__half2*)&v[u].x);
            float2 f1 = __half22float2(*(__half2*)&v[u].y);
            acc.x += f0.x * wv[u];
            acc.y += f0.y * wv[u];
            acc.z += f1.x * wv[u];
            acc.w += f1.y * wv[u];
        }
    }
    for (; j < e; j++) {
        int s   = g_csr_src[j];
        float w = g_csr_w[j];
        uint2 u = __ldg((const uint2*)(h + (size_t)s * 128) + lane);
        float2 f0 = __half22float2(*(__half2*)&u.x);
        float2 f1 = __half22float2(*(__half2*)&u.y);
        acc.x += f0.x * w; acc.y += f0.y * w;
        acc.z += f1.x * w; acc.w += f1.y * w;
    }

    float4 bb = ((const float4*)bias)[lane];
    float4 o;
    o.x = fmaxf(acc.x + bb.x, 0.f);
    o.y = fmaxf(acc.y + bb.y, 0.f);
    o.z = fmaxf(acc.z + bb.z, 0.f);
    o.w = fmaxf(acc.w + bb.w, 0.f);
    if (res) {
        float4 rv = ((const float4*)&res[(size_t)i * 128])[lane];
        o.x += rv.x; o.y += rv.y; o.z += rv.z; o.w += rv.w;
    }
    ((float4*)&out[(size_t)i * 128])[lane] = o;
}

// ---------------- host launcher ----------------
extern "C" void kernel_launch(void* const* d_in, const int* in_sizes, int n_in,
                              void* d_out, int out_size) {
    const float* x  = (const float*)d_in[0];
    const int*   ei = (const int*)d_in[1];
    const float* W0 = (const float*)d_in[2];
    const float* b0 = (const float*)d_in[3];
    const float* W1 = (const float*)d_in[4];
    const float* b1 = (const float*)d_in[5];
    const float* W2 = (const float*)d_in[6];
    const float* b2 = (const float*)d_in[7];
    const float* Wr = (const float*)d_in[8];
    const float* br = (const float*)d_in[9];
    float* out = (float*)d_out;

    const int* src = ei;
    const int* dst = ei + EE;

    float *res_p, *y_p;
    __half* h_p;
    cudaGetSymbolAddress((void**)&res_p, g_res);
    cudaGetSymbolAddress((void**)&h_p, g_h);
    cudaGetSymbolAddress((void**)&y_p, g_y);

    cudaFuncSetAttribute(k_gemm_mma<float>, cudaFuncAttributeMaxDynamicSharedMemorySize, GEMM_SMEM);
    cudaFuncSetAttribute(k_gemm_mma<__half>, cudaFuncAttributeMaxDynamicSharedMemorySize, GEMM_SMEM);

    const int AB = (NN + 7) / 8;
    const int EB = (EE + 255) / 256;
    const int NB = (NN + 255) / 256;

    k_deg_init<<<NB, 256>>>();
    k_count<<<EB, 256>>>(dst);
    k_scan1<<<SCAN_NB, SCAN_TPB>>>();

    // residual GEMM placed 4th (fp32-output variant) — clock canary in the profile:
    // R15 measured this exact kernel at 47.5us / 1.24 TB/s.
    k_gemm_mma<float><<<GEMM_TILES, GEMM_THREADS, GEMM_SMEM>>>(x, Wr, br, res_p, NN);

    k_scan2<<<1, 128>>>();
    k_scan3<<<SCAN_NB, SCAN_TPB>>>();
    k_fill<<<EB, 256>>>(src, dst);

    // layer 0
    k_gemm_mma<__half><<<GEMM_TILES, GEMM_THREADS, GEMM_SMEM>>>(x, W0, nullptr, h_p, NN);
    k_agg<<<AB, 256>>>(h_p, b0, res_p, y_p);

    // layer 1
    k_gemm_mma<__half><<<GEMM_TILES, GEMM_THREADS, GEMM_SMEM>>>(y_p, W1, nullptr, h_p, NN);
    k_agg<<<AB, 256>>>(h_p, b1, nullptr, y_p);

    // layer 2
    k_gemm_mma<__half><<<GEMM_TILES, GEMM_THREADS, GEMM_SMEM>>>(y_p, W2, nullptr, h_p, NN);
    k_agg<<<AB, 256>>>(h_p, b2, nullptr, out);
}

// round 17
// speedup vs baseline: 1.4982x; 1.0294x over previous
#include <cuda_runtime.h>
#include <cuda_bf16.h>
#include <cuda_fp16.h>
#include <cstdint>

#define NN 100000
#define EE 1600000
#define HH 128

#define SCAN_TPB 256
#define SCAN_NPT 4
#define SCAN_NPB (SCAN_TPB * SCAN_NPT)
#define SCAN_NB  ((NN + SCAN_NPB - 1) / SCAN_NPB)

// ---- layer-1/2 GEMM (R8-verified geometry) ----
#define TILE_M 256
#define GEMM_TILES ((NN + TILE_M - 1) / TILE_M)   // 391
#define GEMM_THREADS 512
#define WA  (256 * 64)
#define WB  (128 * 64)
#define OFF_AH 0
#define OFF_AL (WA)
#define OFF_BH (2 * WA)
#define OFF_BL (2 * WA + WB)
#define GEMM_SMEM ((2 * WA + 2 * WB) * 4)   // 192KB

// ---- fused layer-0 GEMM: M-tile 128, N=256 (B = [W0 | Wr]) ----
#define FT_M 128
#define FT_TILES ((NN + FT_M - 1) / FT_M)         // 782
#define FWA (128 * 64)      // 8192 words per A array
#define FWB (256 * 64)      // 16384 words per B array
#define FOFF_AH 0
#define FOFF_AL (FWA)
#define FOFF_BH (2 * FWA)
#define FOFF_BL (2 * FWA + FWB)
#define FGEMM_SMEM ((2 * FWA + 2 * FWB) * 4)      // 192KB

// ---------------- scratch ----------------
__device__ float  g_res[NN * HH];     // residual (fp32)
__device__ __half g_h[NN * HH];       // GEMM output feeding gather (fp16)
__device__ __half g_yh[NN * HH];      // post-agg activation (fp16, feeds GEMM)
__device__ float  g_dinv[NN];
__device__ int    g_deg[NN];
__device__ int    g_rowstart[NN + 1];
__device__ int    g_cursor[NN];
__device__ int    g_csr_src[EE];
__device__ float  g_csr_w[EE];
__device__ int    g_blocksum[SCAN_NB];

// ---------------- helpers ----------------
__device__ __forceinline__ float truncbf(float x) {
    return __uint_as_float(__float_as_uint(x) & 0xFFFF0000u);
}
__device__ __forceinline__ uint32_t packhi(float a, float b) {
    return __byte_perm(__float_as_uint(a), __float_as_uint(b), 0x7632);
}
__device__ __forceinline__ uint32_t packrn(float a, float b) {
    uint32_t d;
    asm("cvt.rn.bf16x2.f32 %0, %1, %2;" : "=r"(d) : "f"(b), "f"(a));
    return d;
}
__device__ __forceinline__ void mma16816(float* c, uint32_t a0, uint32_t a1,
                                         uint32_t a2, uint32_t a3,
                                         uint32_t b0, uint32_t b1) {
    asm volatile(
        "mma.sync.aligned.m16n8k16.row.col.f32.bf16.bf16.f32 "
        "{%0,%1,%2,%3}, {%4,%5,%6,%7}, {%8,%9}, {%0,%1,%2,%3};"
        : "+f"(c[0]), "+f"(c[1]), "+f"(c[2]), "+f"(c[3])
        : "r"(a0), "r"(a1), "r"(a2), "r"(a3), "r"(b0), "r"(b1));
}
// typed 2-element store
__device__ __forceinline__ void st2(float* p, float a, float b) {
    *(float2*)p = make_float2(a, b);
}
__device__ __forceinline__ void st2(__half* p, float a, float b) {
    *(__half2*)p = __floats2half2_rn(a, b);
}
// row-segment load (4 elems at cols 4*lane..4*lane+3), fp32 or fp16 source
__device__ __forceinline__ float4 ldrow4(const float* p, int lane, bool ok) {
    return ok ? __ldg((const float4*)p + lane) : make_float4(0.f, 0.f, 0.f, 0.f);
}
__device__ __forceinline__ float4 ldrow4(const __half* p, int lane, bool ok) {
    if (!ok) return make_float4(0.f, 0.f, 0.f, 0.f);
    uint2 u = __ldg((const uint2*)p + lane);
    float2 f0 = __half22float2(*(__half2*)&u.x);
    float2 f1 = __half22float2(*(__half2*)&u.y);
    return make_float4(f0.x, f0.y, f1.x, f1.y);
}
// agg output store: 4 floats at p
__device__ __forceinline__ void stout4(float* p, float4 o) { *(float4*)p = o; }
__device__ __forceinline__ void stout4(__half* p, float4 o) {
    uint2 u;
    *(__half2*)&u.x = __floats2half2_rn(o.x, o.y);
    *(__half2*)&u.y = __floats2half2_rn(o.z, o.w);
    *(uint2*)p = u;
}

// ---------------- HMMA GEMM (R8-verified): C[M,128] = A[M,128] @ W[128,128] ----------
// 3-term bf16 split. 512 threads = 16 warps; warp tile 32x64 (mg=wid&7, ng=wid>>3).
template <typename InT, typename OutT>
__global__ void __launch_bounds__(GEMM_THREADS) k_gemm_mma(const InT* __restrict__ A,
                                                           const float* __restrict__ W,
                                                           const float* __restrict__ bias,
                                                           OutT* __restrict__ C, int M) {
    extern __shared__ uint32_t smem[];
    uint32_t* sAh = smem + OFF_AH;
    uint32_t* sAl = smem + OFF_AL;
    uint32_t* sBh = smem + OFF_BH;
    uint32_t* sBl = smem + OFF_BL;

    const int tid = threadIdx.x;
    const int wid = tid >> 5;
    const int lane = tid & 31;
    const int row0 = blockIdx.x * TILE_M;

    // ---- stage A ----
    {
#pragma unroll 4
        for (int seg = 0; seg < 16; seg++) {
            int r = wid * 16 + seg;
            int gr = row0 + r;
            float4 v = ldrow4(A + (size_t)gr * 128, lane, gr < M);
            uint32_t sw = (uint32_t)((r & 7) << 2);
            uint32_t base = (uint32_t)r * 64;
            uint32_t w0 = base + (((uint32_t)(2 * lane)) ^ sw);
            uint32_t w1 = base + (((uint32_t)(2 * lane + 1)) ^ sw);
            sAh[w0] = packhi(v.x, v.y);
            sAh[w1] = packhi(v.z, v.w);
            sAl[w0] = packrn(v.x - truncbf(v.x), v.y - truncbf(v.y));
            sAl[w1] = packrn(v.z - truncbf(v.z), v.w - truncbf(v.w));
        }
    }
    // ---- stage W transposed K-major ----
    {
#pragma unroll
        for (int kpi = 0; kpi < 4; kpi++) {
            int kp = wid * 4 + kpi;
            int k = kp * 2;
            const float* r0 = &W[k * 128];
            const float* r1 = &W[(k + 1) * 128];
#pragma unroll
            for (int j = 0; j < 4; j++) {
                int n = lane + 32 * j;
                float w0 = __ldg(&r0[n]);
                float w1 = __ldg(&r1[n]);
                uint32_t phys = (uint32_t)n * 64 + ((uint32_t)kp ^ (uint32_t)((n & 7) << 2));
                sBh[phys] = packhi(w0, w1);
                sBl[phys] = packrn(w0 - truncbf(w0), w1 - truncbf(w1));
            }
        }
    }
    __syncthreads();

    const int mg = wid & 7;
    const int ng = wid >> 3;
    const int qrow = lane >> 2;
    const int qk = lane & 3;
    const uint32_t sw = (uint32_t)(qrow << 2);

    float acc[2][8][4];
#pragma unroll
    for (int rt = 0; rt < 2; rt++)
#pragma unroll
        for (int nt = 0; nt < 8; nt++)
#pragma unroll
            for (int j = 0; j < 4; j++) acc[rt][nt][j] = 0.f;

#pragma unroll
    for (int ks = 0; ks < 8; ks++) {
        uint32_t kw0 = ((uint32_t)(ks * 8 + qk)) ^ sw;
        uint32_t kw1 = ((uint32_t)(ks * 8 + qk + 4)) ^ sw;
        uint32_t ah[2][4], al[2][4];
#pragma unroll
        for (int rt = 0; rt < 2; rt++) {
            uint32_t b0 = (uint32_t)(mg * 32 + rt * 16 + qrow) * 64;
            uint32_t b8 = b0 + 8 * 64;
            ah[rt][0] = sAh[b0 + kw0];
            ah[rt][1] = sAh[b8 + kw0];
            ah[rt][2] = sAh[b0 + kw1];
            ah[rt][3] = sAh[b8 + kw1];
            al[rt][0] = sAl[b0 + kw0];
            al[rt][1] = sAl[b8 + kw0];
            al[rt][2] = sAl[b0 + kw1];
            al[rt][3] = sAl[b8 + kw1];
        }
#pragma unroll
        for (int nt = 0; nt < 8; nt++) {
            uint32_t nb = (uint32_t)(ng * 64 + nt * 8 + qrow) * 64;
            uint32_t bh0 = sBh[nb + kw0];
            uint32_t bh1 = sBh[nb + kw1];
            uint32_t bl0 = sBl[nb + kw0];
            uint32_t bl1 = sBl[nb + kw1];
#pragma unroll
            for (int rt = 0; rt < 2; rt++) {
                mma16816(acc[rt][nt], ah[rt][0], ah[rt][1], ah[rt][2], ah[rt][3], bh0, bh1);
                mma16816(acc[rt][nt], ah[rt][0], ah[rt][1], ah[rt][2], ah[rt][3], bl0, bl1);
                mma16816(acc[rt][nt], al[rt][0], al[rt][1], al[rt][2], al[rt][3], bh0, bh1);
            }
        }
    }

#pragma unroll
    for (int rt = 0; rt < 2; rt++) {
        int r0 = row0 + mg * 32 + rt * 16 + qrow;
#pragma unroll
        for (int nt = 0; nt < 8; nt++) {
            int col = ng * 64 + nt * 8 + qk * 2;
            float bx = 0.f, by = 0.f;
            if (bias) { bx = __ldg(&bias[col]); by = __ldg(&bias[col + 1]); }
            if (r0 < M)
                st2(&C[(size_t)r0 * 128 + col], acc[rt][nt][0] + bx, acc[rt][nt][1] + by);
            if (r0 + 8 < M)
                st2(&C[(size_t)(r0 + 8) * 128 + col], acc[rt][nt][2] + bx, acc[rt][nt][3] + by);
        }
    }
}

// ---------------- fused layer-0 GEMM: [h | res] = x @ [W0 | Wr] ----------------
// M-tile 128, N=256. cols [0,128) -> h (fp16, no bias); cols [128,256) -> res (fp32, +br).
// 16 warps as 4 mg x 4 ng; warp tile 32x64; same swizzle as k_gemm_mma.
__global__ void __launch_bounds__(GEMM_THREADS) k_gemm_fused(const float* __restrict__ A,
                                                             const float* __restrict__ W0,
                                                             const float* __restrict__ Wr,
                                                             const float* __restrict__ br,
                                                             __half* __restrict__ H,
                                                             float* __restrict__ R, int M) {
    extern __shared__ uint32_t smem[];
    uint32_t* sAh = smem + FOFF_AH;
    uint32_t* sAl = smem + FOFF_AL;
    uint32_t* sBh = smem + FOFF_BH;
    uint32_t* sBl = smem + FOFF_BL;

    const int tid = threadIdx.x;
    const int wid = tid >> 5;
    const int lane = tid & 31;
    const int row0 = blockIdx.x * FT_M;

    // ---- stage A: warp w rows w*8..w*8+7 ----
    {
#pragma unroll 4
        for (int seg = 0; seg < 8; seg++) {
            int r = wid * 8 + seg;
            int gr = row0 + r;
            float4 v = ldrow4(A + (size_t)gr * 128, lane, gr < M);
            uint32_t sw = (uint32_t)((r & 7) << 2);
            uint32_t base = (uint32_t)r * 64;
            uint32_t w0 = base + (((uint32_t)(2 * lane)) ^ sw);
            uint32_t w1 = base + (((uint32_t)(2 * lane + 1)) ^ sw);
            sAh[w0] = packhi(v.x, v.y);
            sAh[w1] = packhi(v.z, v.w);
            sAl[w0] = packrn(v.x - truncbf(v.x), v.y - truncbf(v.y));
            sAl[w1] = packrn(v.z - truncbf(v.z), v.w - truncbf(v.w));
        }
    }
    // ---- stage B = [W0 rows 0..127 | Wr rows 128..255], K-major ----
    {
        const int wsel = wid >> 3;                 // 0 -> W0, 1 -> Wr
        const float* Wm = wsel ? Wr : W0;
        const int w8 = wid & 7;
#pragma unroll
        for (int it = 0; it < 8; it++) {
            int kp = w8 * 8 + it;                  // 0..63
            int k = kp * 2;
            const float* r0 = &Wm[k * 128];
            const float* r1 = &Wm[(k + 1) * 128];
#pragma unroll
            for (int j = 0; j < 4; j++) {
                int n = lane + 32 * j;
                int bn = wsel * 128 + n;           // (bn&7)==(n&7)
                float w0 = __ldg(&r0[n]);
                float w1 = __ldg(&r1[n]);
                uint32_t phys = (uint32_t)bn * 64 + ((uint32_t)kp ^ (uint32_t)((n & 7) << 2));
                sBh[phys] = packhi(w0, w1);
                sBl[phys] = packrn(w0 - truncbf(w0), w1 - truncbf(w1));
            }
        }
    }
    __syncthreads();

    const int mg = wid & 3;           // 4 m-groups x 32 rows
    const int ng = wid >> 2;          // 4 n-groups x 64 cols
    const int qrow = lane >> 2;
    const int qk = lane & 3;
    const uint32_t sw = (uint32_t)(qrow << 2);

    float acc[2][8][4];
#pragma unroll
    for (int rt = 0; rt < 2; rt++)
#pragma unroll
        for (int nt = 0; nt < 8; nt++)
#pragma unroll
            for (int j = 0; j < 4; j++) acc[rt][nt][j] = 0.f;

#pragma unroll
    for (int ks = 0; ks < 8; ks++) {
        uint32_t kw0 = ((uint32_t)(ks * 8 + qk)) ^ sw;
        uint32_t kw1 = ((uint32_t)(ks * 8 + qk + 4)) ^ sw;
        uint32_t ah[2][4], al[2][4];
#pragma unroll
        for (int rt = 0; rt < 2; rt++) {
            uint32_t b0 = (uint32_t)(mg * 32 + rt * 16 + qrow) * 64;
            uint32_t b8 = b0 + 8 * 64;
            ah[rt][0] = sAh[b0 + kw0];
            ah[rt][1] = sAh[b8 + kw0];
            ah[rt][2] = sAh[b0 + kw1];
            ah[rt][3] = sAh[b8 + kw1];
            al[rt][0] = sAl[b0 + kw0];
            al[rt][1] = sAl[b8 + kw0];
            al[rt][2] = sAl[b0 + kw1];
            al[rt][3] = sAl[b8 + kw1];
        }
#pragma unroll
        for (int nt = 0; nt < 8; nt++) {
            uint32_t nb = (uint32_t)(ng * 64 + nt * 8 + qrow) * 64;
            uint32_t bh0 = sBh[nb + kw0];
            uint32_t bh1 = sBh[nb + kw1];
            uint32_t bl0 = sBl[nb + kw0];
            uint32_t bl1 = sBl[nb + kw1];
#pragma unroll
            for (int rt = 0; rt < 2; rt++) {
                mma16816(acc[rt][nt], ah[rt][0], ah[rt][1], ah[rt][2], ah[rt][3], bh0, bh1);
                mma16816(acc[rt][nt], ah[rt][0], ah[rt][1], ah[rt][2], ah[rt][3], bl0, bl1);
                mma16816(acc[rt][nt], al[rt][0], al[rt][1], al[rt][2], al[rt][3], bh0, bh1);
            }
        }
    }

    // ---- epilogue: ng<2 -> H (fp16, no bias); ng>=2 -> R (fp32, +br) ----
#pragma unroll
    for (int rt = 0; rt < 2; rt++) {
        int r0 = row0 + mg * 32 + rt * 16 + qrow;
#pragma unroll
        for (int nt = 0; nt < 8; nt++) {
            int col = ng * 64 + nt * 8 + qk * 2;
            if (ng < 2) {
                if (r0 < M)
                    st2(&H[(size_t)r0 * 128 + col], acc[rt][nt][0], acc[rt][nt][1]);
                if (r0 + 8 < M)
                    st2(&H[(size_t)(r0 + 8) * 128 + col], acc[rt][nt][2], acc[rt][nt][3]);
            } else {
                int c = col - 128;
                float bx = __ldg(&br[c]);
                float by = __ldg(&br[c + 1]);
                if (r0 < M)
                    st2(&R[(size_t)r0 * 128 + c], acc[rt][nt][0] + bx, acc[rt][nt][1] + by);
                if (r0 + 8 < M)
                    st2(&R[(size_t)(r0 + 8) * 128 + c], acc[rt][nt][2] + bx, acc[rt][nt][3] + by);
            }
        }
    }
}

// ---------------- graph structure kernels ----------------
__global__ void k_deg_init() {
    int i = blockIdx.x * blockDim.x + threadIdx.x;
    if (i < NN) g_deg[i] = 1;
}
__global__ void k_count(const int* __restrict__ dst) {
    int e = blockIdx.x * blockDim.x + threadIdx.x;
    if (e < EE) atomicAdd(&g_deg[dst[e]], 1);
}
__global__ void __launch_bounds__(SCAN_TPB) k_scan1() {
    __shared__ int ssum[SCAN_TPB];
    int t = threadIdx.x;
    int base = blockIdx.x * SCAN_NPB + t * SCAN_NPT;
    int s = 0;
#pragma unroll
    for (int c = 0; c < SCAN_NPT; c++) {
        int i = base + c;
        if (i < NN) {
            int d = g_deg[i];
            g_dinv[i] = rsqrtf((float)d);
            s += d - 1;
        }
    }
    ssum[t] = s;
    __syncthreads();
    for (int off = SCAN_TPB / 2; off > 0; off >>= 1) {
        if (t < off) ssum[t] += ssum[t + off];
        __syncthreads();
    }
    if (t == 0) g_blocksum[blockIdx.x] = ssum[0];
}
__global__ void k_scan2() {
    __shared__ int sv[SCAN_NB];
    int t = threadIdx.x;
    if (t < SCAN_NB) sv[t] = g_blocksum[t];
    __syncthreads();
    if (t == 0) {
        int run = 0;
        for (int b = 0; b < SCAN_NB; b++) {
            int v = sv[b];
            g_blocksum[b] = run;
            run += v;
        }
        g_rowstart[NN] = EE;
    }
}
__global__ void __launch_bounds__(SCAN_TPB) k_scan3() {
    __shared__ int ssum[SCAN_TPB];
    int t = threadIdx.x;
    int base = blockIdx.x * SCAN_NPB + t * SCAN_NPT;
    int local[SCAN_NPT];
    int s = 0;
#pragma unroll
    for (int c = 0; c < SCAN_NPT; c++) {
        int i = base + c;
        int d = (i < NN) ? (g_deg[i] - 1) : 0;
        local[c] = d;
        s += d;
    }
    ssum[t] = s;
    __syncthreads();
    for (int off = 1; off < SCAN_TPB; off <<= 1) {
        int v = (t >= off) ? ssum[t - off] : 0;
        __syncthreads();
        ssum[t] += v;
        __syncthreads();
    }
    int run = g_blocksum[blockIdx.x] + ssum[t] - s;
#pragma unroll
    for (int c = 0; c < SCAN_NPT; c++) {
        int i = base + c;
        if (i < NN) {
            g_rowstart[i] = run;
            g_cursor[i]   = run;
            run += local[c];
        }
    }
}
__global__ void k_fill(const int* __restrict__ src, const int* __restrict__ dst) {
    int e = blockIdx.x * blockDim.x + threadIdx.x;
    if (e >= EE) return;
    int s = src[e];
    int d = dst[e];
    int pos = atomicAdd(&g_cursor[d], 1);
    g_csr_src[pos] = s;
    g_csr_w[pos]   = g_dinv[s] * g_dinv[d];
}

// ---------------- aggregation: one warp per node, fp16 gather, unroll 8 ----------------
template <typename OutT>
__global__ void __launch_bounds__(256) k_agg(const __half* __restrict__ h,
                                             const float* __restrict__ bias,
                                             const float* __restrict__ res,
                                             OutT* __restrict__ out) {
    int gw = (blockIdx.x * blockDim.x + threadIdx.x) >> 5;
    int lane = threadIdx.x & 31;
    if (gw >= NN) return;
    int i = gw;

    float di = g_dinv[i];
    float wself = di * di;

    float4 acc;
    {
        uint2 u = __ldg((const uint2*)(h + (size_t)i * 128) + lane);
        float2 f0 = __half22float2(*(__half2*)&u.x);
        float2 f1 = __half22float2(*(__half2*)&u.y);
        acc.x = f0.x * wself; acc.y = f0.y * wself;
        acc.z = f1.x * wself; acc.w = f1.y * wself;
    }

    int b = g_rowstart[i];
    int e = g_rowstart[i + 1];
    int j = b;
    for (; j + 8 <= e; j += 8) {
        int sidx[8];
        float wv[8];
#pragma unroll
        for (int u = 0; u < 8; u++) {
            sidx[u] = g_csr_src[j + u];
            wv[u] = g_csr_w[j + u];
        }
        uint2 v[8];
#pragma unroll
        for (int u = 0; u < 8; u++)
            v[u] = __ldg((const uint2*)(h + (size_t)sidx[u] * 128) + lane);
#pragma unroll
        for (int u = 0; u < 8; u++) {
            float2 f0 = __half22float2(*(__half2*)&v[u].x);
            float2 f1 = __half22float2(*(__half2*)&v[u].y);
            acc.x += f0.x * wv[u];
            acc.y += f0.y * wv[u];
            acc.z += f1.x * wv[u];
            acc.w += f1.y * wv[u];
        }
    }
    for (; j < e; j++) {
        int s   = g_csr_src[j];
        float w = g_csr_w[j];
        uint2 u = __ldg((const uint2*)(h + (size_t)s * 128) + lane);
        float2 f0 = __half22float2(*(__half2*)&u.x);
        float2 f1 = __half22float2(*(__half2*)&u.y);
        acc.x += f0.x * w; acc.y += f0.y * w;
        acc.z += f1.x * w; acc.w += f1.y * w;
    }

    float4 bb = ((const float4*)bias)[lane];
    float4 o;
    o.x = fmaxf(acc.x + bb.x, 0.f);
    o.y = fmaxf(acc.y + bb.y, 0.f);
    o.z = fmaxf(acc.z + bb.z, 0.f);
    o.w = fmaxf(acc.w + bb.w, 0.f);
    if (res) {
        float4 rv = ((const float4*)&res[(size_t)i * 128])[lane];
        o.x += rv.x; o.y += rv.y; o.z += rv.z; o.w += rv.w;
    }
    stout4(&out[(size_t)i * 128 + 4 * lane], o);
}

// ---------------- host launcher ----------------
extern "C" void kernel_launch(void* const* d_in, const int* in_sizes, int n_in,
                              void* d_out, int out_size) {
    const float* x  = (const float*)d_in[0];
    const int*   ei = (const int*)d_in[1];
    const float* W0 = (const float*)d_in[2];
    const float* b0 = (const float*)d_in[3];
    const float* W1 = (const float*)d_in[4];
    const float* b1 = (const float*)d_in[5];
    const float* W2 = (const float*)d_in[6];
    const float* b2 = (const float*)d_in[7];
    const float* Wr = (const float*)d_in[8];
    const float* br = (const float*)d_in[9];
    float* out = (float*)d_out;

    const int* src = ei;
    const int* dst = ei + EE;

    float* res_p;
    __half *h_p, *yh_p;
    cudaGetSymbolAddress((void**)&res_p, g_res);
    cudaGetSymbolAddress((void**)&h_p, g_h);
    cudaGetSymbolAddress((void**)&yh_p, g_yh);

    cudaFuncSetAttribute(k_gemm_fused, cudaFuncAttributeMaxDynamicSharedMemorySize, FGEMM_SMEM);
    cudaFuncSetAttribute((const void*)k_gemm_mma<__half, __half>,
                         cudaFuncAttributeMaxDynamicSharedMemorySize, GEMM_SMEM);

    const int AB = (NN + 7) / 8;
    const int EB = (EE + 255) / 256;
    const int NB = (NN + 255) / 256;

    k_deg_init<<<NB, 256>>>();
    k_count<<<EB, 256>>>(dst);
    k_scan1<<<SCAN_NB, SCAN_TPB>>>();

    // fused layer-0 + residual GEMM in the profiled slot (only needs x)
    k_gemm_fused<<<FT_TILES, GEMM_THREADS, FGEMM_SMEM>>>(x, W0, Wr, br, h_p, res_p, NN);

    k_scan2<<<1, 128>>>();
    k_scan3<<<SCAN_NB, SCAN_TPB>>>();
    k_fill<<<EB, 256>>>(src, dst);

    // layer 0 aggregation -> y (fp16)
    k_agg<__half><<<AB, 256>>>(h_p, b0, res_p, yh_p);

    // layer 1
    k_gemm_mma<__half, __half><<<GEMM_TILES, GEMM_THREADS, GEMM_SMEM>>>(yh_p, W1, nullptr, h_p, NN);
    k_agg<__half><<<AB, 256>>>(h_p, b1, nullptr, yh_p);

    // layer 2
    k_gemm_mma<__half, __half><<<GEMM_TILES, GEMM_THREADS, GEMM_SMEM>>>(yh_p, W2, nullptr, h_p, NN);
    k_agg<float><<<AB, 256>>>(h_p, b2, nullptr, out);
}